// round 3
// baseline (speedup 1.0000x reference)
#include <cuda_runtime.h>
#include <cstdint>
#include <cstddef>

// ============================================================
// out = L1rownorm(A[8192,8192]) @ X[8192,512] @ W[512,256] + bias
// Reassociated:
//   Yt[256,8192] = (X @ W)^T        (tf32 mma.sync, rna in registers)
//   out[m,:]     = (A[m,:] @ Y) / sum|A[m,:]| + bias   (rowsum fused)
// tcgen05 unavailable (ptxas targets sm_103 non-a) -> legacy HMMA path.
// ============================================================

#define N_ROWS 8192
#define F_IN   512
#define F_OUT  256

#define TILE_M 128
#define TILE_N 128
#define CHUNK_K 32
#define STAGES 4
#define ROW_PAD 36                              // floats per smem row (conflict-free)
#define STG_FLOATS (TILE_M * ROW_PAD)           // 4608 floats = 18432 B
#define STG_BYTES  (STG_FLOATS * 4)
#define STAGE_BYTES (2 * STG_BYTES)             // A tile + B tile
#define SMEM_TOTAL (STAGES * STAGE_BYTES)       // 147456 B

__device__ __align__(1024) float g_Wt[(size_t)F_OUT * F_IN];
__device__ __align__(1024) float g_Yt[(size_t)F_OUT * N_ROWS];

// ---------------- device helpers ----------------
__device__ __forceinline__ uint32_t f2tf(float f) {
    uint32_t u;
    asm("cvt.rna.tf32.f32 %0, %1;" : "=r"(u) : "f"(f));
    return u;
}
__device__ __forceinline__ void mma8(float* c, const uint32_t* a, const uint32_t* b) {
    asm volatile(
        "mma.sync.aligned.m16n8k8.row.col.f32.tf32.tf32.f32 "
        "{%0,%1,%2,%3}, {%4,%5,%6,%7}, {%8,%9}, {%0,%1,%2,%3};"
        : "+f"(c[0]), "+f"(c[1]), "+f"(c[2]), "+f"(c[3])
        : "r"(a[0]), "r"(a[1]), "r"(a[2]), "r"(a[3]), "r"(b[0]), "r"(b[1]));
}
__device__ __forceinline__ void cpa16(uint32_t s, const float* g) {
    asm volatile("cp.async.cg.shared.global [%0], [%1], 16;" :: "r"(s), "l"(g));
}
__device__ __forceinline__ uint32_t smem_u32(const void* p) {
    uint32_t a;
    asm("{ .reg .u64 t; cvta.to.shared.u64 t, %1; cvt.u32.u64 %0, t; }" : "=r"(a) : "l"(p));
    return a;
}

// ---------------- prep: W[512,256] -> Wt[256,512] ----------------
__global__ void __launch_bounds__(256, 1) prep_wt(const float* __restrict__ w,
                                                  float* __restrict__ wt) {
    int t = blockIdx.x * 256 + threadIdx.x;      // 131072 threads exactly
    int fi = t >> 8, fo = t & 255;
    wt[fo * F_IN + fi] = w[t];
}

// ---------------- unified tf32 GEMM:  C[TILE_M,TILE_N] = P @ Q^T ----------------
// P: [M, K] K-major (stride strideP floats), Q: [N, K] K-major (stride strideQ).
// mode 0: C -> out (raw).  mode 1: C * inv(rowsum|P tile rows|) + bias -> out.
__global__ void __launch_bounds__(256, 1) gemm_tf32(
    const float* __restrict__ P, const float* __restrict__ Q,
    int strideP, int strideQ, int kchunks, int ntiles, int mode,
    float* __restrict__ out, int ostride, const float* __restrict__ bias)
{
    extern __shared__ char smem[];
    const uint32_t sbase = smem_u32(smem);

    const int tid  = threadIdx.x;
    const int lane = tid & 31;
    const int wid  = tid >> 5;
    const int gid  = lane >> 2;      // group id (0..7)
    const int tig  = lane & 3;       // thread in group
    const int wm   = wid & 1;        // warp row (2)
    const int wn   = wid >> 1;       // warp col (4)

    const int mtile = blockIdx.x / ntiles;
    const int ntile = blockIdx.x % ntiles;
    const int m0 = mtile * TILE_M;
    const int n0 = ntile * TILE_N;

    // ---- cp.async issue of one K-chunk (A tile + B tile) ----
    const int r8 = tid >> 3;          // 0..31  (row block)
    const int sg = tid & 7;           // 0..7   (16B segment)
    const float* gPb = P + (size_t)m0 * strideP + sg * 4;
    const float* gQb = Q + (size_t)n0 * strideQ + sg * 4;

    auto issue = [&](int kc, int s) {
        uint32_t sA = sbase + s * STAGE_BYTES + r8 * 144 + sg * 16;
        uint32_t sB = sA + STG_BYTES;
        const float* gA = gPb + (size_t)kc * CHUNK_K;
        const float* gB = gQb + (size_t)kc * CHUNK_K;
        #pragma unroll
        for (int i = 0; i < 4; i++) {
            int row = i * 32 + r8;
            cpa16(sA + i * 32 * 144, gA + (size_t)row * strideP);
            cpa16(sB + i * 32 * 144, gB + (size_t)row * strideQ);
        }
    };

    float acc[4][4][4];
    #pragma unroll
    for (int mi = 0; mi < 4; mi++)
        #pragma unroll
        for (int ni = 0; ni < 4; ni++)
            #pragma unroll
            for (int i = 0; i < 4; i++) acc[mi][ni][i] = 0.f;
    float sr = 0.f;

    // prologue: 3 chunks in flight
    #pragma unroll
    for (int s = 0; s < STAGES - 1; s++) {
        issue(s, s);
        asm volatile("cp.async.commit_group;" ::: "memory");
    }

    const int rsr = tid & 127;        // rowsum: row handled by this thread
    const int rsh = tid >> 7;         // which 16-float half
    const int rsx = (rsr >> 3) & 3;   // xor stagger to avoid bank conflicts

    for (int kc = 0; kc < kchunks; kc++) {
        asm volatile("cp.async.wait_group %0;" :: "n"(STAGES - 2) : "memory");
        __syncthreads();
        const int s = kc & (STAGES - 1);
        const float* As = (const float*)(smem + s * STAGE_BYTES);
        const float* Bs = As + STG_FLOATS;

        if (mode) {  // L1 row sums from the A tile already in smem
            const float* Ar = As + rsr * ROW_PAD + rsh * 16;
            #pragma unroll
            for (int q = 0; q < 4; q++) {
                int qq = q ^ rsx;
                float4 v = *(const float4*)(Ar + qq * 4);
                sr += (fabsf(v.x) + fabsf(v.y)) + (fabsf(v.z) + fabsf(v.w));
            }
        }

        const float* Abase = As + (wm * 64 + gid) * ROW_PAD + tig;
        const float* Bbase = Bs + (wn * 32 + gid) * ROW_PAD + tig;
        #pragma unroll
        for (int k8 = 0; k8 < 4; k8++) {
            uint32_t af[4][4], bf[4][2];
            #pragma unroll
            for (int mi = 0; mi < 4; mi++) {
                const float* p = Abase + mi * 16 * ROW_PAD + k8 * 8;
                af[mi][0] = f2tf(p[0]);
                af[mi][1] = f2tf(p[8 * ROW_PAD]);
                af[mi][2] = f2tf(p[4]);
                af[mi][3] = f2tf(p[8 * ROW_PAD + 4]);
            }
            #pragma unroll
            for (int ni = 0; ni < 4; ni++) {
                const float* p = Bbase + ni * 8 * ROW_PAD + k8 * 8;
                bf[ni][0] = f2tf(p[0]);
                bf[ni][1] = f2tf(p[4]);
            }
            #pragma unroll
            for (int mi = 0; mi < 4; mi++)
                #pragma unroll
                for (int ni = 0; ni < 4; ni++)
                    mma8(acc[mi][ni], af[mi], bf[ni]);
        }

        if (kc + STAGES - 1 < kchunks) issue(kc + STAGES - 1, (kc + STAGES - 1) & (STAGES - 1));
        asm volatile("cp.async.commit_group;" ::: "memory");
    }

    // ---- epilogue ----
    __syncthreads();
    float* rs = (float*)smem;   // reuse stage 0
    if (mode) {
        rs[tid] = sr;
        __syncthreads();
        if (tid < 128) {
            float tsum = rs[tid] + rs[tid + 128];
            rs[tid] = 1.f / fmaxf(tsum, 1e-12f);
        }
        __syncthreads();
    }

    #pragma unroll
    for (int mi = 0; mi < 4; mi++) {
        const int r0 = wm * 64 + mi * 16 + gid;
        float i0 = 1.f, i1 = 1.f;
        if (mode) { i0 = rs[r0]; i1 = rs[r0 + 8]; }
        #pragma unroll
        for (int ni = 0; ni < 4; ni++) {
            const int cg = n0 + wn * 32 + ni * 8 + tig * 2;
            float bx = 0.f, by = 0.f;
            if (mode) { float2 bv = *(const float2*)(bias + (cg - n0)); bx = bv.x; by = bv.y; }
            float2 v0, v1;
            v0.x = acc[mi][ni][0] * i0 + bx;
            v0.y = acc[mi][ni][1] * i0 + by;
            v1.x = acc[mi][ni][2] * i1 + bx;
            v1.y = acc[mi][ni][3] * i1 + by;
            *(float2*)(out + (size_t)(m0 + r0) * ostride + cg) = v0;
            *(float2*)(out + (size_t)(m0 + r0 + 8) * ostride + cg) = v1;
        }
    }
}

// ---------------- host ----------------
extern "C" void kernel_launch(void* const* d_in, const int* in_sizes, int n_in,
                              void* d_out, int out_size) {
    const float *A = nullptr, *X = nullptr, *W = nullptr, *Bi = nullptr;
    for (int i = 0; i < n_in; i++) {
        long s = in_sizes[i];
        if (s == (long)N_ROWS * N_ROWS)      A  = (const float*)d_in[i];
        else if (s == (long)N_ROWS * F_IN)   X  = (const float*)d_in[i];
        else if (s == (long)F_IN * F_OUT)    W  = (const float*)d_in[i];
        else if (s == (long)F_OUT)           Bi = (const float*)d_in[i];
    }

    void *wt = nullptr, *yt = nullptr;
    cudaGetSymbolAddress(&wt, g_Wt);
    cudaGetSymbolAddress(&yt, g_Yt);

    cudaFuncSetAttribute(gemm_tf32, cudaFuncAttributeMaxDynamicSharedMemorySize, SMEM_TOTAL);

    // Wt[256,512] = W^T
    prep_wt<<<(F_IN * F_OUT) / 256, 256>>>(W, (float*)wt);

    // GEMM1: Yt[256,8192] = Wt @ X^T   (M=256 -> 2 mtiles, N=8192 -> 64 ntiles)
    gemm_tf32<<<2 * 64, 256, SMEM_TOTAL>>>(
        (const float*)wt, X, F_IN, F_IN, F_IN / CHUNK_K, 64, 0,
        (float*)yt, N_ROWS, nullptr);

    // GEMM2: out[8192,256] = (A @ Yt^T) * inv_rowsum + bias  (64 mtiles x 2 ntiles)
    gemm_tf32<<<64 * 2, 256, SMEM_TOTAL>>>(
        A, (const float*)yt, N_ROWS, N_ROWS, N_ROWS / CHUNK_K, 2, 1,
        (float*)d_out, F_OUT, Bi);
}

// round 4
// speedup vs baseline: 1.2614x; 1.2614x over previous
#include <cuda_runtime.h>
#include <cuda_fp16.h>
#include <cstdint>
#include <cstddef>

// ============================================================
// out = L1rownorm(A[8192,8192]) @ X[8192,512] @ W[512,256] + bias
// Reassociated:
//   Yt[256,8192] = (X @ W)^T     (tf32 mma, stored fp16)
//   out[m,:]     = (A[m,:] @ Y) / sum|A[m,:]| + bias
// GEMM2 runs fp16 HMMA (m16n8k16, fp32 accum): 2x legacy tf32 rate.
// A converted fp32->fp16 in registers (rna); |v|<~4 so fp16 == tf32 precision.
// ============================================================

#define N_ROWS 8192
#define F_IN   512
#define F_OUT  256

// ---- GEMM1 (tf32) config ----
#define T1_M 128
#define T1_N 128
#define T1_K 32
#define T1_STAGES 4
#define T1_PAD 36
#define T1_STGF (T1_M * T1_PAD)
#define T1_STGB (T1_STGF * 4)
#define T1_STAGE_BYTES (2 * T1_STGB)
#define T1_SMEM (T1_STAGES * T1_STAGE_BYTES)    // 147456

// ---- GEMM2 (fp16) config ----
#define T2_M 128
#define T2_N 64
#define CK 32
#define STG2 3
#define PA 40                                   // floats per A smem row (160B)
#define PB 40                                   // halves per B smem row (80B)
#define A_STAGE_B (T2_M * PA * 4)               // 20480
#define B_STAGE_B (T2_N * PB * 2)               // 5120
#define STAGE2_B (A_STAGE_B + B_STAGE_B)        // 25600
#define T2_SMEM (STG2 * STAGE2_B)               // 76800 -> 2 CTAs/SM

__device__ __align__(1024) float  g_Wt[(size_t)F_OUT * F_IN];
__device__ __align__(1024) __half g_Yt[(size_t)F_OUT * N_ROWS];

// ---------------- device helpers ----------------
__device__ __forceinline__ uint32_t f2tf(float f) {
    uint32_t u;
    asm("cvt.rna.tf32.f32 %0, %1;" : "=r"(u) : "f"(f));
    return u;
}
__device__ __forceinline__ uint32_t pack_h2(float lo, float hi) {
    // PTX: cvt.f16x2 d, a, b -> d.hi = cvt(a), d.lo = cvt(b)
    uint32_t u;
    asm("cvt.rn.f16x2.f32 %0, %1, %2;" : "=r"(u) : "f"(hi), "f"(lo));
    return u;
}
__device__ __forceinline__ void mma_tf32_k8(float* c, const uint32_t* a, const uint32_t* b) {
    asm volatile(
        "mma.sync.aligned.m16n8k8.row.col.f32.tf32.tf32.f32 "
        "{%0,%1,%2,%3}, {%4,%5,%6,%7}, {%8,%9}, {%0,%1,%2,%3};"
        : "+f"(c[0]), "+f"(c[1]), "+f"(c[2]), "+f"(c[3])
        : "r"(a[0]), "r"(a[1]), "r"(a[2]), "r"(a[3]), "r"(b[0]), "r"(b[1]));
}
__device__ __forceinline__ void mma_f16_k16(float* c, const uint32_t* a, const uint32_t* b) {
    asm volatile(
        "mma.sync.aligned.m16n8k16.row.col.f32.f16.f16.f32 "
        "{%0,%1,%2,%3}, {%4,%5,%6,%7}, {%8,%9}, {%0,%1,%2,%3};"
        : "+f"(c[0]), "+f"(c[1]), "+f"(c[2]), "+f"(c[3])
        : "r"(a[0]), "r"(a[1]), "r"(a[2]), "r"(a[3]), "r"(b[0]), "r"(b[1]));
}
__device__ __forceinline__ void cpa16(uint32_t s, const void* g) {
    asm volatile("cp.async.cg.shared.global [%0], [%1], 16;" :: "r"(s), "l"(g));
}
__device__ __forceinline__ uint32_t smem_u32(const void* p) {
    uint32_t a;
    asm("{ .reg .u64 t; cvta.to.shared.u64 t, %1; cvt.u32.u64 %0, t; }" : "=r"(a) : "l"(p));
    return a;
}

// ---------------- prep: W[512,256] -> Wt[256,512] ----------------
__global__ void __launch_bounds__(256, 1) prep_wt(const float* __restrict__ w,
                                                  float* __restrict__ wt) {
    int t = blockIdx.x * 256 + threadIdx.x;
    int fi = t >> 8, fo = t & 255;
    wt[fo * F_IN + fi] = w[t];
}

// ---------------- GEMM1 (tf32): Yt[256,8192](fp16) = Wt @ X^T ----------------
__global__ void __launch_bounds__(256, 1) gemm1_tf32(
    const float* __restrict__ P, const float* __restrict__ Q,
    __half* __restrict__ out)
{
    extern __shared__ char smem[];
    const uint32_t sbase = smem_u32(smem);

    const int tid  = threadIdx.x;
    const int lane = tid & 31;
    const int wid  = tid >> 5;
    const int gid  = lane >> 2;
    const int tig  = lane & 3;
    const int wm   = wid & 1;
    const int wn   = wid >> 1;

    const int mtile = blockIdx.x >> 6;       // 2 mtiles
    const int ntile = blockIdx.x & 63;       // 64 ntiles
    const int m0 = mtile * T1_M;
    const int n0 = ntile * T1_N;
    const int kchunks = F_IN / T1_K;         // 16

    const int r8 = tid >> 3;
    const int sg = tid & 7;
    const float* gPb = P + (size_t)m0 * F_IN + sg * 4;
    const float* gQb = Q + (size_t)n0 * F_IN + sg * 4;

    auto issue = [&](int kc, int s) {
        uint32_t sA = sbase + s * T1_STAGE_BYTES + r8 * (T1_PAD * 4) + sg * 16;
        uint32_t sB = sA + T1_STGB;
        const float* gA = gPb + kc * T1_K;
        const float* gB = gQb + kc * T1_K;
        #pragma unroll
        for (int i = 0; i < 4; i++) {
            int row = i * 32 + r8;
            cpa16(sA + i * 32 * (T1_PAD * 4), gA + (size_t)row * F_IN);
            cpa16(sB + i * 32 * (T1_PAD * 4), gB + (size_t)row * F_IN);
        }
    };

    float acc[4][4][4];
    #pragma unroll
    for (int mi = 0; mi < 4; mi++)
        #pragma unroll
        for (int ni = 0; ni < 4; ni++)
            #pragma unroll
            for (int i = 0; i < 4; i++) acc[mi][ni][i] = 0.f;

    #pragma unroll
    for (int s = 0; s < T1_STAGES - 1; s++) {
        issue(s, s);
        asm volatile("cp.async.commit_group;" ::: "memory");
    }

    for (int kc = 0; kc < kchunks; kc++) {
        asm volatile("cp.async.wait_group %0;" :: "n"(T1_STAGES - 2) : "memory");
        __syncthreads();
        const int s = kc & (T1_STAGES - 1);
        const float* As = (const float*)(smem + s * T1_STAGE_BYTES);
        const float* Bs = As + T1_STGF;

        const float* Abase = As + (wm * 64 + gid) * T1_PAD + tig;
        const float* Bbase = Bs + (wn * 32 + gid) * T1_PAD + tig;
        #pragma unroll
        for (int k8 = 0; k8 < 4; k8++) {
            uint32_t af[4][4], bf[4][2];
            #pragma unroll
            for (int mi = 0; mi < 4; mi++) {
                const float* p = Abase + mi * 16 * T1_PAD + k8 * 8;
                af[mi][0] = f2tf(p[0]);
                af[mi][1] = f2tf(p[8 * T1_PAD]);
                af[mi][2] = f2tf(p[4]);
                af[mi][3] = f2tf(p[8 * T1_PAD + 4]);
            }
            #pragma unroll
            for (int ni = 0; ni < 4; ni++) {
                const float* p = Bbase + ni * 8 * T1_PAD + k8 * 8;
                bf[ni][0] = f2tf(p[0]);
                bf[ni][1] = f2tf(p[4]);
            }
            #pragma unroll
            for (int mi = 0; mi < 4; mi++)
                #pragma unroll
                for (int ni = 0; ni < 4; ni++)
                    mma_tf32_k8(acc[mi][ni], af[mi], bf[ni]);
        }

        if (kc + T1_STAGES - 1 < kchunks) issue(kc + T1_STAGES - 1, (kc + T1_STAGES - 1) & (T1_STAGES - 1));
        asm volatile("cp.async.commit_group;" ::: "memory");
    }

    // epilogue: store fp16
    #pragma unroll
    for (int mi = 0; mi < 4; mi++) {
        const int r0 = wm * 64 + mi * 16 + gid;
        #pragma unroll
        for (int ni = 0; ni < 4; ni++) {
            const int cg = n0 + wn * 32 + ni * 8 + tig * 2;
            uint32_t v0 = pack_h2(acc[mi][ni][0], acc[mi][ni][1]);
            uint32_t v1 = pack_h2(acc[mi][ni][2], acc[mi][ni][3]);
            *(uint32_t*)(out + (size_t)(m0 + r0) * N_ROWS + cg) = v0;
            *(uint32_t*)(out + (size_t)(m0 + r0 + 8) * N_ROWS + cg) = v1;
        }
    }
}

// ---------------- GEMM2 (fp16): out = (A @ Yt^T)*inv_rowsum + bias ----------------
__global__ void __launch_bounds__(256, 2) gemm2_f16(
    const float* __restrict__ A, const __half* __restrict__ Yt,
    float* __restrict__ out, const float* __restrict__ bias)
{
    extern __shared__ char smem[];
    const uint32_t sbase = smem_u32(smem);

    const int tid  = threadIdx.x;
    const int lane = tid & 31;
    const int wid  = tid >> 5;
    const int gid  = lane >> 2;
    const int tig  = lane & 3;
    const int wm   = wid >> 1;          // 0..3 (M)
    const int wn   = wid & 1;           // 0..1 (N)

    const int mtile = blockIdx.x >> 2;  // 64
    const int ntile = blockIdx.x & 3;   // 4
    const int m0 = mtile * T2_M;
    const int n0 = ntile * T2_N;
    const int kchunks = N_ROWS / CK;    // 256

    // cp.async mappings
    const int ra = tid >> 3;            // 0..31  A row block
    const int sa = tid & 7;             // 0..7   A 16B seg
    const int rb = tid >> 2;            // 0..63  B row
    const int sb = tid & 3;             // 0..3   B 16B seg
    const float*  gA0 = A  + (size_t)(m0) * N_ROWS + sa * 4;
    const __half* gB0 = Yt + (size_t)(n0 + rb) * N_ROWS + sb * 8;

    auto issue = [&](int kc, int s) {
        uint32_t sA = sbase + s * STAGE2_B + ra * (PA * 4) + sa * 16;
        const float* gA = gA0 + kc * CK;
        #pragma unroll
        for (int i = 0; i < 4; i++)
            cpa16(sA + i * 32 * (PA * 4), gA + (size_t)(i * 32 + ra) * N_ROWS);
        uint32_t sB = sbase + s * STAGE2_B + A_STAGE_B + rb * (PB * 2) + sb * 16;
        cpa16(sB, gB0 + kc * CK);
    };

    float acc[2][4][4];
    #pragma unroll
    for (int mi = 0; mi < 2; mi++)
        #pragma unroll
        for (int ni = 0; ni < 4; ni++)
            #pragma unroll
            for (int i = 0; i < 4; i++) acc[mi][ni][i] = 0.f;
    float sr0 = 0.f, sr1 = 0.f;

    issue(0, 0);
    asm volatile("cp.async.commit_group;" ::: "memory");
    issue(1, 1);
    asm volatile("cp.async.commit_group;" ::: "memory");

    // rowsum mapping: 2 threads per row, 16 floats each, staggered float4 reads
    const int rsr = tid & 127;
    const int rsh = tid >> 7;
    const int stag = (rsr >> 2) & 3;

    int s_c = 0, s_p = 2;
    for (int kc = 0; kc < kchunks; kc++) {
        asm volatile("cp.async.wait_group %0;" :: "n"(1) : "memory");
        __syncthreads();
        const float*  As = (const float*)(smem + s_c * STAGE2_B);
        const __half* Bs = (const __half*)(smem + s_c * STAGE2_B + A_STAGE_B);

        {   // L1 row-sums from the A tile already in smem
            const float* Ar = As + rsr * PA + rsh * 16;
            #pragma unroll
            for (int q = 0; q < 4; q += 2) {
                int q0 = (q + stag) & 3, q1 = (q + 1 + stag) & 3;
                float4 v0 = *(const float4*)(Ar + q0 * 4);
                float4 v1 = *(const float4*)(Ar + q1 * 4);
                sr0 += (fabsf(v0.x) + fabsf(v0.y)) + (fabsf(v0.z) + fabsf(v0.w));
                sr1 += (fabsf(v1.x) + fabsf(v1.y)) + (fabsf(v1.z) + fabsf(v1.w));
            }
        }

        const float* Abase = As + (wm * 32 + gid) * PA + 2 * tig;
        const __half* Bbase = Bs + (wn * 32 + gid) * PB + 2 * tig;
        #pragma unroll
        for (int ks = 0; ks < 2; ks++) {
            uint32_t af[2][4], bf[4][2];
            #pragma unroll
            for (int mi = 0; mi < 2; mi++) {
                const float* p = Abase + mi * 16 * PA + ks * 16;
                float2 v00 = *(const float2*)(p);
                float2 v01 = *(const float2*)(p + 8 * PA);
                float2 v10 = *(const float2*)(p + 8);
                float2 v11 = *(const float2*)(p + 8 * PA + 8);
                af[mi][0] = pack_h2(v00.x, v00.y);
                af[mi][1] = pack_h2(v01.x, v01.y);
                af[mi][2] = pack_h2(v10.x, v10.y);
                af[mi][3] = pack_h2(v11.x, v11.y);
            }
            #pragma unroll
            for (int ni = 0; ni < 4; ni++) {
                const __half* p = Bbase + ni * 8 * PB + ks * 16;
                bf[ni][0] = *(const uint32_t*)(p);
                bf[ni][1] = *(const uint32_t*)(p + 8);
            }
            #pragma unroll
            for (int mi = 0; mi < 2; mi++)
                #pragma unroll
                for (int ni = 0; ni < 4; ni++)
                    mma_f16_k16(acc[mi][ni], af[mi], bf[ni]);
        }

        if (kc + 2 < kchunks) issue(kc + 2, s_p);
        asm volatile("cp.async.commit_group;" ::: "memory");
        if (++s_c == STG2) s_c = 0;
        if (++s_p == STG2) s_p = 0;
    }

    // ---- epilogue ----
    __syncthreads();
    float* rs = (float*)smem;
    rs[tid] = sr0 + sr1;
    __syncthreads();
    if (tid < 128) {
        float tsum = rs[tid] + rs[tid + 128];
        rs[tid] = 1.f / fmaxf(tsum, 1e-12f);
    }
    __syncthreads();

    #pragma unroll
    for (int mi = 0; mi < 2; mi++) {
        const int r0 = wm * 32 + mi * 16 + gid;
        const float i0 = rs[r0];
        const float i1 = rs[r0 + 8];
        #pragma unroll
        for (int ni = 0; ni < 4; ni++) {
            const int cg = n0 + wn * 32 + ni * 8 + tig * 2;
            float2 bv = *(const float2*)(bias + cg);
            float2 v0, v1;
            v0.x = acc[mi][ni][0] * i0 + bv.x;
            v0.y = acc[mi][ni][1] * i0 + bv.y;
            v1.x = acc[mi][ni][2] * i1 + bv.x;
            v1.y = acc[mi][ni][3] * i1 + bv.y;
            *(float2*)(out + (size_t)(m0 + r0) * F_OUT + cg) = v0;
            *(float2*)(out + (size_t)(m0 + r0 + 8) * F_OUT + cg) = v1;
        }
    }
}

// ---------------- host ----------------
extern "C" void kernel_launch(void* const* d_in, const int* in_sizes, int n_in,
                              void* d_out, int out_size) {
    const float *A = nullptr, *X = nullptr, *W = nullptr, *Bi = nullptr;
    for (int i = 0; i < n_in; i++) {
        long s = in_sizes[i];
        if (s == (long)N_ROWS * N_ROWS)      A  = (const float*)d_in[i];
        else if (s == (long)N_ROWS * F_IN)   X  = (const float*)d_in[i];
        else if (s == (long)F_IN * F_OUT)    W  = (const float*)d_in[i];
        else if (s == (long)F_OUT)           Bi = (const float*)d_in[i];
    }

    void *wt = nullptr, *yt = nullptr;
    cudaGetSymbolAddress(&wt, g_Wt);
    cudaGetSymbolAddress(&yt, g_Yt);

    cudaFuncSetAttribute(gemm1_tf32, cudaFuncAttributeMaxDynamicSharedMemorySize, T1_SMEM);
    cudaFuncSetAttribute(gemm2_f16,  cudaFuncAttributeMaxDynamicSharedMemorySize, T2_SMEM);

    prep_wt<<<(F_IN * F_OUT) / 256, 256>>>(W, (float*)wt);

    // GEMM1: Yt[256,8192](fp16) = Wt @ X^T
    gemm1_tf32<<<2 * 64, 256, T1_SMEM>>>((const float*)wt, X, (__half*)yt);

    // GEMM2: out[8192,256] = (A @ Yt^T) * inv_rowsum + bias
    gemm2_f16<<<64 * 4, 256, T2_SMEM>>>(A, (const __half*)yt, (float*)d_out, Bi);
}

// round 5
// speedup vs baseline: 1.2743x; 1.0102x over previous
#include <cuda_runtime.h>
#include <cuda_fp16.h>
#include <cstdint>
#include <cstddef>

// ============================================================
// out = L1rownorm(A[8192,8192]) @ X[8192,512] @ W[512,256] + bias
//   Yt[256,8192] = (X @ W)^T        (tf32 mma, stored fp16)
//   out[m,:]     = (A[m,:] @ Y) / sum(A[m,:]) + bias   (A >= 0)
// GEMM2: fp16 HMMA, A converted fp32->fp16 in registers (producer),
// rowsum accumulated in producer registers (zero extra smem traffic).
// ============================================================

#define N_ROWS 8192
#define F_IN   512
#define F_OUT  256

// ---- GEMM1 (tf32) config ----
#define T1_M 128
#define T1_N 128
#define T1_K 32
#define T1_STAGES 4
#define T1_PAD 36
#define T1_STGF (T1_M * T1_PAD)
#define T1_STGB (T1_STGF * 4)
#define T1_STAGE_BYTES (2 * T1_STGB)
#define T1_SMEM (T1_STAGES * T1_STAGE_BYTES)    // 147456

// ---- GEMM2 (fp16) config ----
#define T2_M 128
#define T2_N 64
#define CK 32
#define PAH 40                                  // halves per smem row (80 B)
#define A_ST  (T2_M * PAH * 2)                  // 10240 B per A stage
#define B_ST  (T2_N * PAH * 2)                  // 5120 B per B stage
#define B_OFF (2 * A_ST)                        // 20480
#define RS_OFF (B_OFF + 3 * B_ST)               // 35840
#define T2_SMEM (RS_OFF + 128 * 4)              // 36352

__device__ __align__(1024) float  g_Wt[(size_t)F_OUT * F_IN];
__device__ __align__(1024) __half g_Yt[(size_t)F_OUT * N_ROWS];

// ---------------- device helpers ----------------
__device__ __forceinline__ uint32_t f2tf(float f) {
    uint32_t u;
    asm("cvt.rna.tf32.f32 %0, %1;" : "=r"(u) : "f"(f));
    return u;
}
__device__ __forceinline__ uint32_t pack_h2(float lo, float hi) {
    uint32_t u;
    asm("cvt.rn.f16x2.f32 %0, %1, %2;" : "=r"(u) : "f"(hi), "f"(lo));
    return u;
}
__device__ __forceinline__ void mma_tf32_k8(float* c, const uint32_t* a, const uint32_t* b) {
    asm volatile(
        "mma.sync.aligned.m16n8k8.row.col.f32.tf32.tf32.f32 "
        "{%0,%1,%2,%3}, {%4,%5,%6,%7}, {%8,%9}, {%0,%1,%2,%3};"
        : "+f"(c[0]), "+f"(c[1]), "+f"(c[2]), "+f"(c[3])
        : "r"(a[0]), "r"(a[1]), "r"(a[2]), "r"(a[3]), "r"(b[0]), "r"(b[1]));
}
__device__ __forceinline__ void mma_f16_k16(float* c, const uint32_t* a, const uint32_t* b) {
    asm volatile(
        "mma.sync.aligned.m16n8k16.row.col.f32.f16.f16.f32 "
        "{%0,%1,%2,%3}, {%4,%5,%6,%7}, {%8,%9}, {%0,%1,%2,%3};"
        : "+f"(c[0]), "+f"(c[1]), "+f"(c[2]), "+f"(c[3])
        : "r"(a[0]), "r"(a[1]), "r"(a[2]), "r"(a[3]), "r"(b[0]), "r"(b[1]));
}
__device__ __forceinline__ void cpa16(uint32_t s, const void* g) {
    asm volatile("cp.async.cg.shared.global [%0], [%1], 16;" :: "r"(s), "l"(g));
}
__device__ __forceinline__ void ldsm4(uint32_t& r0, uint32_t& r1, uint32_t& r2, uint32_t& r3,
                                      uint32_t addr) {
    asm volatile("ldmatrix.sync.aligned.m8n8.x4.shared.b16 {%0,%1,%2,%3}, [%4];"
                 : "=r"(r0), "=r"(r1), "=r"(r2), "=r"(r3) : "r"(addr));
}
__device__ __forceinline__ uint32_t smem_u32(const void* p) {
    uint32_t a;
    asm("{ .reg .u64 t; cvta.to.shared.u64 t, %1; cvt.u32.u64 %0, t; }" : "=r"(a) : "l"(p));
    return a;
}

// ---------------- prep: W[512,256] -> Wt[256,512] ----------------
__global__ void __launch_bounds__(256, 1) prep_wt(const float* __restrict__ w,
                                                  float* __restrict__ wt) {
    int t = blockIdx.x * 256 + threadIdx.x;
    int fi = t >> 8, fo = t & 255;
    wt[fo * F_IN + fi] = w[t];
}

// ---------------- GEMM1 (tf32): Yt[256,8192](fp16) = Wt @ X^T ----------------
__global__ void __launch_bounds__(256, 1) gemm1_tf32(
    const float* __restrict__ P, const float* __restrict__ Q,
    __half* __restrict__ out)
{
    extern __shared__ char smem[];
    const uint32_t sbase = smem_u32(smem);

    const int tid  = threadIdx.x;
    const int lane = tid & 31;
    const int wid  = tid >> 5;
    const int gid  = lane >> 2;
    const int tig  = lane & 3;
    const int wm   = wid & 1;
    const int wn   = wid >> 1;

    const int mtile = blockIdx.x >> 6;
    const int ntile = blockIdx.x & 63;
    const int m0 = mtile * T1_M;
    const int n0 = ntile * T1_N;
    const int kchunks = F_IN / T1_K;

    const int r8 = tid >> 3;
    const int sg = tid & 7;
    const float* gPb = P + (size_t)m0 * F_IN + sg * 4;
    const float* gQb = Q + (size_t)n0 * F_IN + sg * 4;

    auto issue = [&](int kc, int s) {
        uint32_t sA = sbase + s * T1_STAGE_BYTES + r8 * (T1_PAD * 4) + sg * 16;
        uint32_t sB = sA + T1_STGB;
        const float* gA = gPb + kc * T1_K;
        const float* gB = gQb + kc * T1_K;
        #pragma unroll
        for (int i = 0; i < 4; i++) {
            int row = i * 32 + r8;
            cpa16(sA + i * 32 * (T1_PAD * 4), gA + (size_t)row * F_IN);
            cpa16(sB + i * 32 * (T1_PAD * 4), gB + (size_t)row * F_IN);
        }
    };

    float acc[4][4][4];
    #pragma unroll
    for (int mi = 0; mi < 4; mi++)
        #pragma unroll
        for (int ni = 0; ni < 4; ni++)
            #pragma unroll
            for (int i = 0; i < 4; i++) acc[mi][ni][i] = 0.f;

    #pragma unroll
    for (int s = 0; s < T1_STAGES - 1; s++) {
        issue(s, s);
        asm volatile("cp.async.commit_group;" ::: "memory");
    }

    for (int kc = 0; kc < kchunks; kc++) {
        asm volatile("cp.async.wait_group %0;" :: "n"(T1_STAGES - 2) : "memory");
        __syncthreads();
        const int s = kc & (T1_STAGES - 1);
        const float* As = (const float*)(smem + s * T1_STAGE_BYTES);
        const float* Bs = As + T1_STGF;

        const float* Abase = As + (wm * 64 + gid) * T1_PAD + tig;
        const float* Bbase = Bs + (wn * 32 + gid) * T1_PAD + tig;
        #pragma unroll
        for (int k8 = 0; k8 < 4; k8++) {
            uint32_t af[4][4], bf[4][2];
            #pragma unroll
            for (int mi = 0; mi < 4; mi++) {
                const float* p = Abase + mi * 16 * T1_PAD + k8 * 8;
                af[mi][0] = f2tf(p[0]);
                af[mi][1] = f2tf(p[8 * T1_PAD]);
                af[mi][2] = f2tf(p[4]);
                af[mi][3] = f2tf(p[8 * T1_PAD + 4]);
            }
            #pragma unroll
            for (int ni = 0; ni < 4; ni++) {
                const float* p = Bbase + ni * 8 * T1_PAD + k8 * 8;
                bf[ni][0] = f2tf(p[0]);
                bf[ni][1] = f2tf(p[4]);
            }
            #pragma unroll
            for (int mi = 0; mi < 4; mi++)
                #pragma unroll
                for (int ni = 0; ni < 4; ni++)
                    mma_tf32_k8(acc[mi][ni], af[mi], bf[ni]);
        }

        if (kc + T1_STAGES - 1 < kchunks) issue(kc + T1_STAGES - 1, (kc + T1_STAGES - 1) & (T1_STAGES - 1));
        asm volatile("cp.async.commit_group;" ::: "memory");
    }

    #pragma unroll
    for (int mi = 0; mi < 4; mi++) {
        const int r0 = wm * 64 + mi * 16 + gid;
        #pragma unroll
        for (int ni = 0; ni < 4; ni++) {
            const int cg = n0 + wn * 32 + ni * 8 + tig * 2;
            uint32_t v0 = pack_h2(acc[mi][ni][0], acc[mi][ni][1]);
            uint32_t v1 = pack_h2(acc[mi][ni][2], acc[mi][ni][3]);
            *(uint32_t*)(out + (size_t)(m0 + r0) * N_ROWS + cg) = v0;
            *(uint32_t*)(out + (size_t)(m0 + r0 + 8) * N_ROWS + cg) = v1;
        }
    }
}

// ---------------- GEMM2 (fp16): out = (A @ Yt^T)*inv_rowsum + bias ----------------
__global__ void __launch_bounds__(256, 2) gemm2_f16(
    const float* __restrict__ A, const __half* __restrict__ Yt,
    float* __restrict__ out, const float* __restrict__ bias)
{
    extern __shared__ char smem[];
    const uint32_t sbase = smem_u32(smem);

    const int tid  = threadIdx.x;
    const int lane = tid & 31;
    const int wid  = tid >> 5;
    const int gid  = lane >> 2;
    const int tig  = lane & 3;
    const int wm   = wid >> 1;            // 0..3 (M strips of 32)
    const int wn   = wid & 1;             // 0..1 (N strips of 32)

    const int mtile = blockIdx.x >> 2;    // 64
    const int ntile = blockIdx.x & 3;     // 4
    const int m0 = mtile * T2_M;
    const int n0 = ntile * T2_N;
    const int kchunks = N_ROWS / CK;      // 256

    // ---- producer mappings ----
    const int ra = tid >> 3;              // 0..31  (A row mod 32)
    const int sa = tid & 7;               // 0..7   (A 4-float segment)
    const int rb = tid >> 2;              // 0..63  (B row)
    const int sb = tid & 3;               // 0..3   (B 16B segment)
    const float*  gA = A  + (size_t)(m0 + ra) * N_ROWS + sa * 4;
    const __half* gB = Yt + (size_t)(n0 + rb) * N_ROWS + sb * 8;

    // ldmatrix lane mapping
    const int lrow = lane & 15;
    const int lhi  = (lane >> 4) & 1;

    float acc[2][4][4];
    #pragma unroll
    for (int mi = 0; mi < 2; mi++)
        #pragma unroll
        for (int ni = 0; ni < 4; ni++)
            #pragma unroll
            for (int i = 0; i < 4; i++) acc[mi][ni][i] = 0.f;
    float rsum[4] = {0.f, 0.f, 0.f, 0.f};

    // prologue: prefetch A chunk 0 into registers, B chunks 0,1 via cp.async
    float4 v[4];
    #pragma unroll
    for (int i = 0; i < 4; i++)
        v[i] = *(const float4*)(gA + (size_t)i * 32 * N_ROWS);
    cpa16(sbase + B_OFF + 0 * B_ST + rb * (PAH * 2) + sb * 16, gB);
    asm volatile("cp.async.commit_group;" ::: "memory");
    cpa16(sbase + B_OFF + 1 * B_ST + rb * (PAH * 2) + sb * 16, gB + CK);
    asm volatile("cp.async.commit_group;" ::: "memory");

    int s3 = 0;   // kc % 3
    int sp = 2;   // (kc+2) % 3
    for (int kc = 0; kc < kchunks; kc++) {
        const int s2 = kc & 1;
        asm volatile("cp.async.wait_group %0;" :: "n"(1) : "memory");

        // ---- producer: STS fp16 A, accumulate rowsum, prefetch next ----
        const uint32_t aw = sbase + s2 * A_ST + ra * (PAH * 2) + sa * 8;
        #pragma unroll
        for (int i = 0; i < 4; i++) {
            uint32_t h01 = pack_h2(v[i].x, v[i].y);
            uint32_t h23 = pack_h2(v[i].z, v[i].w);
            asm volatile("st.shared.v2.b32 [%0], {%1,%2};"
                         :: "r"(aw + i * 32 * (PAH * 2)), "r"(h01), "r"(h23));
            rsum[i] += (v[i].x + v[i].y) + (v[i].z + v[i].w);
        }
        const int kn = (kc + 1 < kchunks) ? kc + 1 : kchunks - 1;
        #pragma unroll
        for (int i = 0; i < 4; i++)
            v[i] = *(const float4*)(gA + (size_t)i * 32 * N_ROWS + (size_t)kn * CK);

        __syncthreads();

        // ---- consumer: ldmatrix + MMA ----
        const uint32_t aBase = sbase + s2 * A_ST;
        const uint32_t bBase = sbase + B_OFF + s3 * B_ST;
        #pragma unroll
        for (int ks = 0; ks < 2; ks++) {
            uint32_t af[2][4], bf[4][2];
            #pragma unroll
            for (int mi = 0; mi < 2; mi++) {
                uint32_t ad = aBase +
                    ((wm * 32 + mi * 16 + lrow) * PAH + ks * 16 + lhi * 8) * 2;
                ldsm4(af[mi][0], af[mi][1], af[mi][2], af[mi][3], ad);
            }
            #pragma unroll
            for (int np = 0; np < 2; np++) {
                uint32_t bd = bBase +
                    ((wn * 32 + np * 16 + lrow) * PAH + ks * 16 + lhi * 8) * 2;
                uint32_t r0, r1, r2, r3;
                ldsm4(r0, r1, r2, r3, bd);
                bf[np * 2 + 0][0] = r0; bf[np * 2 + 0][1] = r2;
                bf[np * 2 + 1][0] = r1; bf[np * 2 + 1][1] = r3;
            }
            #pragma unroll
            for (int mi = 0; mi < 2; mi++)
                #pragma unroll
                for (int ni = 0; ni < 4; ni++)
                    mma_f16_k16(acc[mi][ni], af[mi], bf[ni]);
        }

        // issue B for kc+2
        if (kc + 2 < kchunks)
            cpa16(sbase + B_OFF + sp * B_ST + rb * (PAH * 2) + sb * 16,
                  gB + (size_t)(kc + 2) * CK);
        asm volatile("cp.async.commit_group;" ::: "memory");
        if (++s3 == 3) s3 = 0;
        if (++sp == 3) sp = 0;
    }

    // ---- rowsum reduce (8 lanes per row group) ----
    #pragma unroll
    for (int i = 0; i < 4; i++) {
        rsum[i] += __shfl_down_sync(0xffffffffu, rsum[i], 4, 8);
        rsum[i] += __shfl_down_sync(0xffffffffu, rsum[i], 2, 8);
        rsum[i] += __shfl_down_sync(0xffffffffu, rsum[i], 1, 8);
    }
    float* rs = (float*)(smem + RS_OFF);
    if (sa == 0) {
        #pragma unroll
        for (int i = 0; i < 4; i++)
            rs[i * 32 + ra] = 1.f / fmaxf(rsum[i], 1e-12f);
    }
    __syncthreads();

    // ---- epilogue ----
    #pragma unroll
    for (int mi = 0; mi < 2; mi++) {
        const int r0 = wm * 32 + mi * 16 + gid;
        const float i0 = rs[r0];
        const float i1 = rs[r0 + 8];
        #pragma unroll
        for (int ni = 0; ni < 4; ni++) {
            const int cg = n0 + wn * 32 + ni * 8 + tig * 2;
            float2 bv = *(const float2*)(bias + cg);
            float2 v0, v1;
            v0.x = acc[mi][ni][0] * i0 + bv.x;
            v0.y = acc[mi][ni][1] * i0 + bv.y;
            v1.x = acc[mi][ni][2] * i1 + bv.x;
            v1.y = acc[mi][ni][3] * i1 + bv.y;
            *(float2*)(out + (size_t)(m0 + r0) * F_OUT + cg) = v0;
            *(float2*)(out + (size_t)(m0 + r0 + 8) * F_OUT + cg) = v1;
        }
    }
}

// ---------------- host ----------------
extern "C" void kernel_launch(void* const* d_in, const int* in_sizes, int n_in,
                              void* d_out, int out_size) {
    const float *A = nullptr, *X = nullptr, *W = nullptr, *Bi = nullptr;
    for (int i = 0; i < n_in; i++) {
        long s = in_sizes[i];
        if (s == (long)N_ROWS * N_ROWS)      A  = (const float*)d_in[i];
        else if (s == (long)N_ROWS * F_IN)   X  = (const float*)d_in[i];
        else if (s == (long)F_IN * F_OUT)    W  = (const float*)d_in[i];
        else if (s == (long)F_OUT)           Bi = (const float*)d_in[i];
    }

    void *wt = nullptr, *yt = nullptr;
    cudaGetSymbolAddress(&wt, g_Wt);
    cudaGetSymbolAddress(&yt, g_Yt);

    cudaFuncSetAttribute(gemm1_tf32, cudaFuncAttributeMaxDynamicSharedMemorySize, T1_SMEM);
    cudaFuncSetAttribute(gemm2_f16,  cudaFuncAttributeMaxDynamicSharedMemorySize, T2_SMEM);

    prep_wt<<<(F_IN * F_OUT) / 256, 256>>>(W, (float*)wt);
    gemm1_tf32<<<2 * 64, 256, T1_SMEM>>>((const float*)wt, X, (__half*)yt);
    gemm2_f16<<<64 * 4, 256, T2_SMEM>>>(A, (const __half*)yt, (float*)d_out, Bi);
}

// round 6
// speedup vs baseline: 1.5711x; 1.2329x over previous
#include <cuda_runtime.h>
#include <cuda_fp16.h>
#include <cstdint>
#include <cstddef>

// ============================================================
// out = L1rownorm(A[8192,8192]) @ X[8192,512] @ W[512,256] + bias
//   Xh = fp16(X), Wth = fp16(W^T)
//   Yt[256,8192](fp16) = Wth @ Xh^T          (fp16 HMMA)
//   out[m,:] = (A[m,:] @ Y) / sum(A[m,:]) + bias   (A >= 0, rowsum fused)
// ============================================================

#define N_ROWS 8192
#define F_IN   512
#define F_OUT  256

// ---- GEMM1 (fp16, cp.async both operands) ----
#define G1_ST  (128 * 40 * 2)        // 10240 B per operand stage (128 rows x 80B)
#define G1_STAGE (2 * G1_ST)         // A + B
#define G1_SMEM (3 * G1_STAGE)       // 61440

// ---- GEMM2 (fp16) ----
#define T2_M 128
#define T2_N 64
#define CK 32
#define PAH 40                       // halves per smem row (80 B)
#define A_ST  (T2_M * PAH * 2)       // 10240 B per A stage
#define B_ST  (T2_N * PAH * 2)       // 5120 B per B stage
#define B_OFF (4 * A_ST)             // 40960 (4 A stages)
#define RS_OFF (B_OFF + 8 * B_ST)    // 81920 (8 B stages)
#define T2_SMEM (RS_OFF + 128 * 4)   // 82432 -> 2 CTAs/SM

__device__ __align__(1024) __half g_Xh[(size_t)N_ROWS * F_IN];
__device__ __align__(1024) __half g_Wth[(size_t)F_OUT * F_IN];
__device__ __align__(1024) __half g_Yt[(size_t)F_OUT * N_ROWS];

// ---------------- device helpers ----------------
__device__ __forceinline__ uint32_t pack_h2(float lo, float hi) {
    uint32_t u;
    asm("cvt.rn.f16x2.f32 %0, %1, %2;" : "=r"(u) : "f"(hi), "f"(lo));
    return u;
}
__device__ __forceinline__ void mma_f16_k16(float* c, const uint32_t* a, const uint32_t* b) {
    asm volatile(
        "mma.sync.aligned.m16n8k16.row.col.f32.f16.f16.f32 "
        "{%0,%1,%2,%3}, {%4,%5,%6,%7}, {%8,%9}, {%0,%1,%2,%3};"
        : "+f"(c[0]), "+f"(c[1]), "+f"(c[2]), "+f"(c[3])
        : "r"(a[0]), "r"(a[1]), "r"(a[2]), "r"(a[3]), "r"(b[0]), "r"(b[1]));
}
__device__ __forceinline__ void cpa16(uint32_t s, const void* g) {
    asm volatile("cp.async.cg.shared.global [%0], [%1], 16;" :: "r"(s), "l"(g));
}
__device__ __forceinline__ void ldsm4(uint32_t& r0, uint32_t& r1, uint32_t& r2, uint32_t& r3,
                                      uint32_t addr) {
    asm volatile("ldmatrix.sync.aligned.m8n8.x4.shared.b16 {%0,%1,%2,%3}, [%4];"
                 : "=r"(r0), "=r"(r1), "=r"(r2), "=r"(r3) : "r"(addr));
}
__device__ __forceinline__ uint32_t smem_u32(const void* p) {
    uint32_t a;
    asm("{ .reg .u64 t; cvta.to.shared.u64 t, %1; cvt.u32.u64 %0, t; }" : "=r"(a) : "l"(p));
    return a;
}

// ---------------- prep kernels ----------------
__global__ void __launch_bounds__(256, 1) prep_xh(const float* __restrict__ x,
                                                  __half* __restrict__ xh) {
    int i = blockIdx.x * 256 + threadIdx.x;           // over float4s
    float4 v = reinterpret_cast<const float4*>(x)[i];
    uint2 o;
    o.x = pack_h2(v.x, v.y);
    o.y = pack_h2(v.z, v.w);
    reinterpret_cast<uint2*>(xh)[i] = o;
}
__global__ void __launch_bounds__(256, 1) prep_wh(const float* __restrict__ w,
                                                  __half* __restrict__ wth) {
    int t = blockIdx.x * 256 + threadIdx.x;           // t = fo*512 + fi
    int fi = t & 511, fo = t >> 9;
    wth[t] = __float2half_rn(w[fi * F_OUT + fo]);
}

// ---------------- GEMM1 (fp16): Yt[256,8192] = Wth @ Xh^T ----------------
__global__ void __launch_bounds__(256, 1) gemm1_f16(
    const __half* __restrict__ P, const __half* __restrict__ Q,
    __half* __restrict__ out)
{
    extern __shared__ char smem[];
    const uint32_t sbase = smem_u32(smem);

    const int tid  = threadIdx.x;
    const int lane = tid & 31;
    const int wid  = tid >> 5;
    const int gid  = lane >> 2;
    const int tig  = lane & 3;
    const int wm   = wid >> 1;            // 0..3 (M strips of 32)
    const int wn   = wid & 1;             // 0..1 (N strips of 64)
    const int lrow = lane & 15;
    const int lhi  = (lane >> 4) & 1;

    const int mtile = blockIdx.x >> 6;    // 2
    const int ntile = blockIdx.x & 63;    // 64
    const int m0 = mtile * 128;
    const int n0 = ntile * 128;
    const int kchunks = F_IN / CK;        // 16

    // cp.async mapping: row = tid>>2 (+64), seg = tid&3 (16B of 64B row)
    const int rw = tid >> 2;
    const int sg = tid & 3;
    const __half* gA = P + (size_t)(m0 + rw) * F_IN + sg * 8;
    const __half* gB = Q + (size_t)(n0 + rw) * F_IN + sg * 8;

    auto issue = [&](int kc, int s) {
        uint32_t sA = sbase + s * G1_STAGE + rw * 80 + sg * 16;
        uint32_t sB = sA + G1_ST;
        cpa16(sA,              gA + kc * CK);
        cpa16(sA + 64 * 80,    gA + kc * CK + (size_t)64 * F_IN);
        cpa16(sB,              gB + kc * CK);
        cpa16(sB + 64 * 80,    gB + kc * CK + (size_t)64 * F_IN);
        asm volatile("cp.async.commit_group;" ::: "memory");
    };

    float acc[2][8][4];
    #pragma unroll
    for (int mi = 0; mi < 2; mi++)
        #pragma unroll
        for (int ni = 0; ni < 8; ni++)
            #pragma unroll
            for (int i = 0; i < 4; i++) acc[mi][ni][i] = 0.f;

    issue(0, 0);
    issue(1, 1);

    int s_c = 0, s_p = 2;
    for (int kc = 0; kc < kchunks; kc++) {
        asm volatile("cp.async.wait_group %0;" :: "n"(1) : "memory");
        __syncthreads();
        const uint32_t aBase = sbase + s_c * G1_STAGE;
        const uint32_t bBase = aBase + G1_ST;

        #pragma unroll
        for (int ks = 0; ks < 2; ks++) {
            uint32_t af[2][4], bf[8][2];
            #pragma unroll
            for (int mi = 0; mi < 2; mi++) {
                uint32_t ad = aBase + ((wm * 32 + mi * 16 + lrow) * PAH + ks * 16 + lhi * 8) * 2;
                ldsm4(af[mi][0], af[mi][1], af[mi][2], af[mi][3], ad);
            }
            #pragma unroll
            for (int np = 0; np < 4; np++) {
                uint32_t bd = bBase + ((wn * 64 + np * 16 + lrow) * PAH + ks * 16 + lhi * 8) * 2;
                uint32_t r0, r1, r2, r3;
                ldsm4(r0, r1, r2, r3, bd);
                bf[np * 2 + 0][0] = r0; bf[np * 2 + 0][1] = r2;
                bf[np * 2 + 1][0] = r1; bf[np * 2 + 1][1] = r3;
            }
            #pragma unroll
            for (int mi = 0; mi < 2; mi++)
                #pragma unroll
                for (int ni = 0; ni < 8; ni++)
                    mma_f16_k16(acc[mi][ni], af[mi], bf[ni]);
        }

        if (kc + 2 < kchunks) issue(kc + 2, s_p);
        else asm volatile("cp.async.commit_group;" ::: "memory");
        if (++s_c == 3) s_c = 0;
        if (++s_p == 3) s_p = 0;
    }

    // epilogue: store fp16 Yt
    #pragma unroll
    for (int mi = 0; mi < 2; mi++) {
        const int r0 = m0 + wm * 32 + mi * 16 + gid;
        #pragma unroll
        for (int ni = 0; ni < 8; ni++) {
            const int cg = n0 + wn * 64 + ni * 8 + tig * 2;
            *(uint32_t*)(out + (size_t)r0 * N_ROWS + cg) =
                pack_h2(acc[mi][ni][0], acc[mi][ni][1]);
            *(uint32_t*)(out + (size_t)(r0 + 8) * N_ROWS + cg) =
                pack_h2(acc[mi][ni][2], acc[mi][ni][3]);
        }
    }
}

// ---------------- GEMM2 (fp16): out = (A @ Yt^T)*inv_rowsum + bias ----------------
__global__ void __launch_bounds__(256, 2) gemm2_f16(
    const float* __restrict__ A, const __half* __restrict__ Yt,
    float* __restrict__ out, const float* __restrict__ bias)
{
    extern __shared__ char smem[];
    const uint32_t sbase = smem_u32(smem);

    const int tid  = threadIdx.x;
    const int lane = tid & 31;
    const int wid  = tid >> 5;
    const int gid  = lane >> 2;
    const int tig  = lane & 3;
    const int wm   = wid >> 1;            // 0..3 (M strips of 32)
    const int wn   = wid & 1;             // 0..1 (N strips of 32)
    const int lrow = lane & 15;
    const int lhi  = (lane >> 4) & 1;

    const int mtile = blockIdx.x >> 2;    // 64
    const int ntile = blockIdx.x & 3;     // 4
    const int m0 = mtile * T2_M;
    const int n0 = ntile * T2_N;
    const int kchunks = N_ROWS / CK;      // 256

    // producer mappings
    const int ra = tid >> 3;              // 0..31  (A row mod 32)
    const int sa = tid & 7;               // 0..7   (A 4-float segment)
    const int rb = tid >> 2;              // 0..63  (B row)
    const int sb = tid & 3;               // 0..3   (B 16B segment)
    const float*  gA = A  + (size_t)(m0 + ra) * N_ROWS + sa * 4;
    const __half* gB = Yt + (size_t)(n0 + rb) * N_ROWS + sb * 8;

    float acc[2][4][4];
    #pragma unroll
    for (int mi = 0; mi < 2; mi++)
        #pragma unroll
        for (int ni = 0; ni < 4; ni++)
            #pragma unroll
            for (int i = 0; i < 4; i++) acc[mi][ni][i] = 0.f;
    float rsum[4] = {0.f, 0.f, 0.f, 0.f};

    // B issue: 2 chunks per commit group
    auto issueB = [&](int kc) {
        if (kc < kchunks) {
            cpa16(sbase + B_OFF + (kc & 7) * B_ST + rb * (PAH * 2) + sb * 16,
                  gB + (size_t)kc * CK);
            cpa16(sbase + B_OFF + ((kc + 1) & 7) * B_ST + rb * (PAH * 2) + sb * 16,
                  gB + (size_t)(kc + 1) * CK);
        }
        asm volatile("cp.async.commit_group;" ::: "memory");
    };
    // A LDG of one chunk into 4 float4 regs
    auto ldA = [&](int kc, float4* v) {
        #pragma unroll
        for (int i = 0; i < 4; i++)
            v[i] = *(const float4*)(gA + (size_t)i * 32 * N_ROWS + (size_t)kc * CK);
    };
    // A STS (fp16 convert) + rowsum
    auto stA = [&](int kc, const float4* v) {
        const uint32_t aw = sbase + (kc & 3) * A_ST + ra * (PAH * 2) + sa * 8;
        #pragma unroll
        for (int i = 0; i < 4; i++) {
            uint32_t h01 = pack_h2(v[i].x, v[i].y);
            uint32_t h23 = pack_h2(v[i].z, v[i].w);
            asm volatile("st.shared.v2.b32 [%0], {%1,%2};"
                         :: "r"(aw + i * 32 * (PAH * 2)), "r"(h01), "r"(h23));
            rsum[i] += (v[i].x + v[i].y) + (v[i].z + v[i].w);
        }
    };
    // full MMA for one chunk
    auto mmaChunk = [&](int kc) {
        const uint32_t aBase = sbase + (kc & 3) * A_ST;
        const uint32_t bBase = sbase + B_OFF + (kc & 7) * B_ST;
        #pragma unroll
        for (int ks = 0; ks < 2; ks++) {
            uint32_t af[2][4], bf[4][2];
            #pragma unroll
            for (int mi = 0; mi < 2; mi++) {
                uint32_t ad = aBase + ((wm * 32 + mi * 16 + lrow) * PAH + ks * 16 + lhi * 8) * 2;
                ldsm4(af[mi][0], af[mi][1], af[mi][2], af[mi][3], ad);
            }
            #pragma unroll
            for (int np = 0; np < 2; np++) {
                uint32_t bd = bBase + ((wn * 32 + np * 16 + lrow) * PAH + ks * 16 + lhi * 8) * 2;
                uint32_t r0, r1, r2, r3;
                ldsm4(r0, r1, r2, r3, bd);
                bf[np * 2 + 0][0] = r0; bf[np * 2 + 0][1] = r2;
                bf[np * 2 + 1][0] = r1; bf[np * 2 + 1][1] = r3;
            }
            #pragma unroll
            for (int mi = 0; mi < 2; mi++)
                #pragma unroll
                for (int ni = 0; ni < 4; ni++)
                    mma_f16_k16(acc[mi][ni], af[mi], bf[ni]);
        }
    };

    // prologue
    float4 vA0[4], vA1[4];
    ldA(0, vA0);
    ldA(1, vA1);
    issueB(0);   // chunks 0,1
    issueB(2);   // chunks 2,3

    for (int kc = 0; kc < kchunks; kc += 2) {
        asm volatile("cp.async.wait_group %0;" :: "n"(1) : "memory");

        stA(kc, vA0);
        stA(kc + 1, vA1);
        int kn0 = kc + 2, kn1 = kc + 3;
        if (kn1 >= kchunks) { kn0 = kchunks - 2; kn1 = kchunks - 1; }
        ldA(kn0, vA0);
        ldA(kn1, vA1);

        __syncthreads();

        issueB(kc + 4);     // chunks kc+4, kc+5 (or empty commit)

        mmaChunk(kc);
        mmaChunk(kc + 1);
    }

    // rowsum reduce (8 lanes per row group)
    #pragma unroll
    for (int i = 0; i < 4; i++) {
        rsum[i] += __shfl_down_sync(0xffffffffu, rsum[i], 4, 8);
        rsum[i] += __shfl_down_sync(0xffffffffu, rsum[i], 2, 8);
        rsum[i] += __shfl_down_sync(0xffffffffu, rsum[i], 1, 8);
    }
    float* rs = (float*)(smem + RS_OFF);
    if (sa == 0) {
        #pragma unroll
        for (int i = 0; i < 4; i++)
            rs[i * 32 + ra] = 1.f / fmaxf(rsum[i], 1e-12f);
    }
    __syncthreads();

    // epilogue
    #pragma unroll
    for (int mi = 0; mi < 2; mi++) {
        const int r0 = wm * 32 + mi * 16 + gid;
        const float i0 = rs[r0];
        const float i1 = rs[r0 + 8];
        #pragma unroll
        for (int ni = 0; ni < 4; ni++) {
            const int cg = n0 + wn * 32 + ni * 8 + tig * 2;
            float2 bv = *(const float2*)(bias + cg);
            float2 v0, v1;
            v0.x = acc[mi][ni][0] * i0 + bv.x;
            v0.y = acc[mi][ni][1] * i0 + bv.y;
            v1.x = acc[mi][ni][2] * i1 + bv.x;
            v1.y = acc[mi][ni][3] * i1 + bv.y;
            *(float2*)(out + (size_t)(m0 + r0) * F_OUT + cg) = v0;
            *(float2*)(out + (size_t)(m0 + r0 + 8) * F_OUT + cg) = v1;
        }
    }
}

// ---------------- host ----------------
extern "C" void kernel_launch(void* const* d_in, const int* in_sizes, int n_in,
                              void* d_out, int out_size) {
    const float *A = nullptr, *X = nullptr, *W = nullptr, *Bi = nullptr;
    for (int i = 0; i < n_in; i++) {
        long s = in_sizes[i];
        if (s == (long)N_ROWS * N_ROWS)      A  = (const float*)d_in[i];
        else if (s == (long)N_ROWS * F_IN)   X  = (const float*)d_in[i];
        else if (s == (long)F_IN * F_OUT)    W  = (const float*)d_in[i];
        else if (s == (long)F_OUT)           Bi = (const float*)d_in[i];
    }

    void *xh = nullptr, *wth = nullptr, *yt = nullptr;
    cudaGetSymbolAddress(&xh, g_Xh);
    cudaGetSymbolAddress(&wth, g_Wth);
    cudaGetSymbolAddress(&yt, g_Yt);

    cudaFuncSetAttribute(gemm1_f16, cudaFuncAttributeMaxDynamicSharedMemorySize, G1_SMEM);
    cudaFuncSetAttribute(gemm2_f16, cudaFuncAttributeMaxDynamicSharedMemorySize, T2_SMEM);

    prep_xh<<<(N_ROWS * F_IN / 4) / 256, 256>>>(X, (__half*)xh);
    prep_wh<<<(F_IN * F_OUT) / 256, 256>>>(W, (__half*)wth);

    // GEMM1: Yt[256,8192] = Wth @ Xh^T   (2 x 64 CTAs)
    gemm1_f16<<<2 * 64, 256, G1_SMEM>>>((const __half*)wth, (const __half*)xh, (__half*)yt);

    // GEMM2: out[8192,256] = (A @ Yt^T) * inv_rowsum + bias   (64 x 4 CTAs)
    gemm2_f16<<<64 * 4, 256, T2_SMEM>>>(A, (const __half*)yt, (float*)d_out, Bi);
}